// round 4
// baseline (speedup 1.0000x reference)
#include <cuda_runtime.h>
#include <math.h>

// Problem constants (fixed by the dataset instance)
#define HD    1024          // hidden
#define NL4   4             // num_label
#define SEQ   512           // sequence length
#define NRW   64            // bsz * num_label
#define LO    256           // capacity for option length (actual <= 212)
#define LDC   512           // capacity for doc length (actual <= 449, and <= SEQ always)
#define NPAIR (NRW*3)       // 192 (i,j) cross-option pairs
#define MR    (NRW*LO)      // 16384 rows
#define NEGV  -1e30f

// ---------------------------------------------------------------------------
// Static device scratch (allocation-free rule: __device__ globals)
// ---------------------------------------------------------------------------
__device__ float g_opt_enc[MR*HD];              // 64 MB
__device__ int   g_opt_mask[MR];
__device__ float g_doc_enc[NRW*LDC*HD];         // 128 MB
__device__ int   g_doc_mask[NRW*LDC];
__device__ float g_logitOpt[NPAIR*LO*LO];       // 48 MB  (becomes aw in place)
__device__ float g_attnOpt[NPAIR*LO*HD];        // 192 MB
__device__ float g_X[MR*7*HD];                  // 448 MB (concat scratch, reused)
__device__ float g_corr[MR*HD];                 // 64 MB
__device__ float g_option[MR*HD];               // 64 MB
__device__ float g_logitD[NRW*LO*LDC];          // 32 MB  (becomes aw in place)
__device__ float g_kq[NRW*LO*LDC];              // 32 MB
__device__ float g_attnD[MR*HD];                // 64 MB
__device__ float g_cow[NRW*LO*LO];              // 16 MB
__device__ float g_coattn[MR*HD];               // 64 MB
__device__ float g_fusion[MR*HD];               // 64 MB
__device__ float g_logitS[NRW*LO*LO];           // 16 MB (becomes aw in place)
__device__ float g_attn2[MR*HD];                // 64 MB
__device__ float g_fusion2[MR*HD];              // 64 MB
__device__ float g_rowq[MR];
__device__ float g_rowk[MR];
__device__ float g_rowkd[NRW*LDC];

// ---------------------------------------------------------------------------
// fp dtype sniff: reference declares int64 but the harness dtype set suggests
// int32. Values are in [300, 450] (never 0), so:
//   int64 layout -> word 1 (high half of element 0) == 0
//   int32 layout -> word 1 == fp[1] in [300,450] != 0
// ---------------------------------------------------------------------------
__device__ __forceinline__ int read_fp(const int* __restrict__ p, int n)
{
    return (p[1] == 0) ? p[2*n] : p[n];
}

// ---------------------------------------------------------------------------
// Build kernels
// ---------------------------------------------------------------------------
__global__ void k_build_opt(const float* __restrict__ ll, const int* __restrict__ am,
                            const int* __restrict__ fpw)
{
    int o = blockIdx.x;     // 0..LO-1
    int n = blockIdx.y;     // 0..NRW-1
    int t = threadIdx.x;    // 0..255 -> float4 over HD
    int fp = read_fp(fpw, n);
    int idx = fp + o;
    int valid = (idx >= 0) && (idx < SEQ);
    int idxc = valid ? idx : (SEQ - 1);
    int m = valid && (am[n*SEQ + idxc] > 0);
    const float4* src = (const float4*)(ll + (size_t)(n*SEQ + idxc) * HD);
    float4* dst = (float4*)(g_opt_enc + (size_t)(n*LO + o) * HD);
    float4 v = m ? src[t] : make_float4(0.f,0.f,0.f,0.f);
    dst[t] = v;
    if (t == 0) g_opt_mask[n*LO + o] = m;
}

__global__ void k_build_doc(const float* __restrict__ ll, const int* __restrict__ am,
                            const int* __restrict__ fpw)
{
    int t0 = blockIdx.x;    // 0..LDC-1
    int n = blockIdx.y;
    int t = threadIdx.x;
    int fp = read_fp(fpw, n);
    int m = (t0 < fp) && (am[n*SEQ + t0] > 0);
    const float4* src = (const float4*)(ll + (size_t)(n*SEQ + t0) * HD);
    float4* dst = (float4*)(g_doc_enc + (size_t)(n*LDC + t0) * HD);
    float4 v = m ? src[t] : make_float4(0.f,0.f,0.f,0.f);
    dst[t] = v;
    if (t == 0) g_doc_mask[n*LDC + t0] = m;
}

// out[r] = dot(X[r,:], w)  over HD
__global__ void k_rowdot(const float* __restrict__ X, const float* __restrict__ w,
                         float* __restrict__ out)
{
    int r = blockIdx.x;
    const float* x = X + (size_t)r * HD;
    float s = 0.f;
    for (int i = threadIdx.x; i < HD; i += 256) s += x[i] * w[i];
    __shared__ float sh[256];
    sh[threadIdx.x] = s; __syncthreads();
    for (int st = 128; st > 0; st >>= 1) {
        if (threadIdx.x < st) sh[threadIdx.x] += sh[threadIdx.x + st];
        __syncthreads();
    }
    if (threadIdx.x == 0) out[r] = sh[0];
}

// ---------------------------------------------------------------------------
// GEMMs: 128x128x8 tiles, 256 threads, 8x8 per thread.
// All M,N multiples of 128; all K multiples of 8 (by construction).
// ---------------------------------------------------------------------------
// NT: C[m,n] = sum_k A[m,k] * B[n,k] (both K-contiguous).
// EPI: 0=none 1=tanh(+bias) 2=relu(+bias) 3=gate-combine 4=trilinear logits
template<int EPI>
__global__ __launch_bounds__(256) void k_gemm_nt(
    const float* __restrict__ A, const float* __restrict__ B, float* __restrict__ C,
    int M, int N, int K,
    long sA, long sB, long sC,
    const float* __restrict__ colScale,
    const float* __restrict__ bias,
    const float* __restrict__ ql, const float* __restrict__ kl,
    const int* __restrict__ mq, const int* __restrict__ mk,
    long sQl, long sKl,
    const float* __restrict__ E1, const float* __restrict__ E2,
    int pairMode)
{
    __shared__ float As[8][128];
    __shared__ float Bs[8][128];
    const int z = blockIdx.z;
    long offA, offB, offC, offQl, offKl;
    if (pairMode) {
        int n = z / 3, jj = z % 3;
        int b = n / NL4, i = n % NL4;
        int j = jj + (jj >= i ? 1 : 0);
        int mb = b * NL4 + j;
        offA = (long)n * LO * HD; offB = (long)mb * LO * HD;
        offC = (long)z * M * N;
        offQl = (long)n * LO; offKl = (long)mb * LO;
    } else {
        offA = z * sA; offB = z * sB; offC = z * sC;
        offQl = z * sQl; offKl = z * sKl;
    }
    const float* Ab = A + offA;
    const float* Bb = B + offB;
    const int tid = threadIdx.x;
    const int bm = blockIdx.y * 128, bn = blockIdx.x * 128;
    const int lr = tid >> 1, lc = (tid & 1) * 4;
    const int ty = tid >> 4, tx = tid & 15;
    float acc[8][8];
#pragma unroll
    for (int i = 0; i < 8; i++)
#pragma unroll
        for (int j = 0; j < 8; j++) acc[i][j] = 0.f;

    for (int k0 = 0; k0 < K; k0 += 8) {
        float4 av = *(const float4*)(Ab + (size_t)(bm + lr) * K + k0 + lc);
        float4 bv = *(const float4*)(Bb + (size_t)(bn + lr) * K + k0 + lc);
        if (EPI == 4) {
            bv.x *= colScale[k0 + lc];     bv.y *= colScale[k0 + lc + 1];
            bv.z *= colScale[k0 + lc + 2]; bv.w *= colScale[k0 + lc + 3];
        }
        As[lc][lr] = av.x; As[lc+1][lr] = av.y; As[lc+2][lr] = av.z; As[lc+3][lr] = av.w;
        Bs[lc][lr] = bv.x; Bs[lc+1][lr] = bv.y; Bs[lc+2][lr] = bv.z; Bs[lc+3][lr] = bv.w;
        __syncthreads();
#pragma unroll
        for (int kk = 0; kk < 8; kk++) {
            float a[8], b[8];
#pragma unroll
            for (int u = 0; u < 8; u++) { a[u] = As[kk][ty*8+u]; b[u] = Bs[kk][tx*8+u]; }
#pragma unroll
            for (int i = 0; i < 8; i++)
#pragma unroll
                for (int j = 0; j < 8; j++) acc[i][j] += a[i] * b[j];
        }
        __syncthreads();
    }
#pragma unroll
    for (int i = 0; i < 8; i++) {
        int m = bm + ty * 8 + i;
#pragma unroll
        for (int j = 0; j < 8; j++) {
            int nn = bn + tx * 8 + j;
            size_t ci = (size_t)offC + (size_t)m * N + nn;
            float v = acc[i][j];
            if (EPI == 0) C[ci] = v;
            else if (EPI == 1) C[ci] = tanhf(v + bias[nn]);
            else if (EPI == 2) C[ci] = fmaxf(v + bias[nn], 0.f);
            else if (EPI == 3) {
                float g = 1.f / (1.f + expf(-(v + bias[nn])));
                C[ci] = E1[ci] * g + E2[ci] * (1.f - g);
            } else {
                v += ql[offQl + m] + kl[offKl + nn];
                C[ci] = (mq[offQl + m] && mk[offKl + nn]) ? v : NEGV;
            }
        }
    }
}

// NN: C[m,h] = sum_k A[m,k] * B[k,h].  ldb == N for all our uses.
__global__ __launch_bounds__(256) void k_gemm_nn(
    const float* __restrict__ A, const float* __restrict__ B, float* __restrict__ C,
    int M, int N, int K, long sA, long sB, long sC, int pairMode)
{
    __shared__ float As[8][128];
    __shared__ float Bs[8][128];
    int z = blockIdx.z;
    long offA, offB, offC;
    if (pairMode) {
        int n = z / 3, jj = z % 3;
        int b = n / NL4, i = n % NL4;
        int j = jj + (jj >= i ? 1 : 0);
        int mb = b * NL4 + j;
        offA = (long)z * LO * LO; offB = (long)mb * LO * HD; offC = (long)z * LO * HD;
    } else { offA = z * sA; offB = z * sB; offC = z * sC; }
    const float* Ab = A + offA;
    const float* Bb = B + offB;
    int tid = threadIdx.x;
    int bm = blockIdx.y * 128, bn = blockIdx.x * 128;
    int lr = tid >> 1, lc = (tid & 1) * 4;
    int br = tid >> 5, bc = (tid & 31) * 4;
    int ty = tid >> 4, tx = tid & 15;
    float acc[8][8];
#pragma unroll
    for (int i = 0; i < 8; i++)
#pragma unroll
        for (int j = 0; j < 8; j++) acc[i][j] = 0.f;

    for (int k0 = 0; k0 < K; k0 += 8) {
        float4 av = *(const float4*)(Ab + (size_t)(bm + lr) * K + k0 + lc);
        As[lc][lr] = av.x; As[lc+1][lr] = av.y; As[lc+2][lr] = av.z; As[lc+3][lr] = av.w;
        float4 bv = *(const float4*)(Bb + (size_t)(k0 + br) * N + bn + bc);
        *(float4*)&Bs[br][bc] = bv;
        __syncthreads();
#pragma unroll
        for (int kk = 0; kk < 8; kk++) {
            float a[8], b[8];
#pragma unroll
            for (int u = 0; u < 8; u++) { a[u] = As[kk][ty*8+u]; b[u] = Bs[kk][tx*8+u]; }
#pragma unroll
            for (int i = 0; i < 8; i++)
#pragma unroll
                for (int j = 0; j < 8; j++) acc[i][j] += a[i] * b[j];
        }
        __syncthreads();
    }
#pragma unroll
    for (int i = 0; i < 8; i++) {
        int m = bm + ty * 8 + i;
#pragma unroll
        for (int j = 0; j < 8; j++) {
            int nn = bn + tx * 8 + j;
            C[(size_t)offC + (size_t)m * N + nn] = acc[i][j];
        }
    }
}

// ---------------------------------------------------------------------------
// Softmax kernels
// ---------------------------------------------------------------------------
__global__ void k_row_softmax(float* __restrict__ X, int Cdim,
    const int* __restrict__ mqb, const int* __restrict__ mkb,
    long sX, long sMq, long sMk, int pairMode)
{
    int z = blockIdx.y, row = blockIdx.x;
    long offX, offMq, offMk;
    if (pairMode) {
        int n = z / 3, jj = z % 3;
        int b = n / NL4, i = n % NL4;
        int j = jj + (jj >= i ? 1 : 0);
        int mb = b * NL4 + j;
        offX = (long)z * LO * LO; offMq = (long)n * LO; offMk = (long)mb * LO;
    } else { offX = z * sX; offMq = z * sMq; offMk = z * sMk; }
    float* x = X + offX + (long)row * Cdim;
    const int* mk = mkb + offMk;
    int qm = mqb[offMq + row];
    int tid = threadIdx.x;
    __shared__ float sh[256];
    float mx = -3.4e38f;
    for (int c = tid; c < Cdim; c += 256) mx = fmaxf(mx, x[c]);
    sh[tid] = mx; __syncthreads();
    for (int s = 128; s > 0; s >>= 1) {
        if (tid < s) sh[tid] = fmaxf(sh[tid], sh[tid + s]);
        __syncthreads();
    }
    mx = sh[0]; __syncthreads();
    float sum = 0.f;
    for (int c = tid; c < Cdim; c += 256) sum += expf(x[c] - mx);
    sh[tid] = sum; __syncthreads();
    for (int s = 128; s > 0; s >>= 1) {
        if (tid < s) sh[tid] += sh[tid + s];
        __syncthreads();
    }
    float inv = 1.f / sh[0];
    for (int c = tid; c < Cdim; c += 256) {
        float e = expf(x[c] - mx);
        x[c] = (qm && mk[c]) ? e * inv : 0.f;
    }
}

// softmax over the q axis (axis=1) of logitD[n][o][t], producing kq (masked).
__global__ void k_col_softmax()
{
    int n = blockIdx.y;
    int t = blockIdx.x * 256 + threadIdx.x;   // < LDC
    const float* x = g_logitD + (size_t)n * LO * LDC;
    float mx = -3.4e38f;
    for (int o = 0; o < LO; o++) mx = fmaxf(mx, x[(size_t)o * LDC + t]);
    float sum = 0.f;
    for (int o = 0; o < LO; o++) sum += expf(x[(size_t)o * LDC + t] - mx);
    float inv = 1.f / sum;
    int km = g_doc_mask[n*LDC + t];
    float* y = g_kq + (size_t)n * LO * LDC;
    for (int o = 0; o < LO; o++) {
        float e = expf(x[(size_t)o * LDC + t] - mx);
        y[(size_t)o * LDC + t] = (km && g_opt_mask[n*LO + o]) ? e * inv : 0.f;
    }
}

// ---------------------------------------------------------------------------
// Elementwise concat builders + final max
// ---------------------------------------------------------------------------
__global__ void k_feats()   // comp input: [cur, cur*aj, cur-aj (x3)] -> 7H
{
    size_t idx = (size_t)blockIdx.x * 256 + threadIdx.x;   // MR*HD total
    size_t r = idx >> 10;
    int h = (int)(idx & 1023);
    int n = (int)(r >> 8);
    int o = (int)(r & 255);
    float cur = g_opt_enc[idx];
    float* xr = g_X + r * (7*HD);
    xr[h] = cur;
#pragma unroll
    for (int jj = 0; jj < 3; jj++) {
        float a = g_attnOpt[(((size_t)(n*3 + jj) * LO + o) << 10) + h];
        xr[(1 + 2*jj)*HD + h] = cur * a;
        xr[(2 + 2*jj)*HD + h] = cur - a;
    }
}

__global__ void k_concat2()  // gate input: [opt_enc, corr]
{
    size_t idx = (size_t)blockIdx.x * 256 + threadIdx.x;
    size_t r = idx >> 10;
    int h = (int)(idx & 1023);
    float* xr = g_X + r * (2*HD);
    xr[h] = g_opt_enc[idx];
    xr[HD + h] = g_corr[idx];
}

__global__ void k_concat3()  // attn_fc input: [option, attn, coattn]
{
    size_t idx = (size_t)blockIdx.x * 256 + threadIdx.x;
    size_t r = idx >> 10;
    int h = (int)(idx & 1023);
    float* xr = g_X + r * (3*HD);
    xr[h] = g_option[idx];
    xr[HD + h] = g_attnD[idx];
    xr[2*HD + h] = g_coattn[idx];
}

__global__ void k_concat4()  // self_fc input: [f, a, f*a, f-a]
{
    size_t idx = (size_t)blockIdx.x * 256 + threadIdx.x;
    size_t r = idx >> 10;
    int h = (int)(idx & 1023);
    float f = g_fusion[idx];
    float a = g_attn2[idx];
    float* xr = g_X + r * (4*HD);
    xr[h] = f;
    xr[HD + h] = a;
    xr[2*HD + h] = f * a;
    xr[3*HD + h] = f - a;
}

__global__ void k_final(float* __restrict__ out)
{
    int n = blockIdx.y;
    int h = blockIdx.x * 256 + threadIdx.x;
    float mx = NEGV;
    for (int o = 0; o < LO; o++) {
        if (g_opt_mask[n*LO + o])
            mx = fmaxf(mx, g_fusion2[((size_t)(n*LO + o) << 10) + h]);
    }
    out[(size_t)n * HD + h] = mx;
}

// ---------------------------------------------------------------------------
// Launch
// ---------------------------------------------------------------------------
extern "C" void kernel_launch(void* const* d_in, const int* in_sizes, int n_in,
                              void* d_out, int out_size)
{
    const float* ll  = (const float*)d_in[0];
    const int*   am  = (const int*)d_in[1];
    const int*   fpw = (const int*)d_in[2];   // int32 or int64; sniffed on device
    // Robust base detection (established: base resolves to 3 when num_label is
    // not a tensor input; keeps working if a scalar tensor appears at slot 3).
    int base = (in_sizes[3] <= 8) ? 4 : 3;
    const float* attn_w1   = (const float*)d_in[base+0];
    const float* attn_w2   = (const float*)d_in[base+1];
    const float* attn_w3   = (const float*)d_in[base+2];
    const float* opt_w1    = (const float*)d_in[base+3];
    const float* opt_w2    = (const float*)d_in[base+4];
    const float* opt_w3    = (const float*)d_in[base+5];
    const float* self_w1   = (const float*)d_in[base+6];
    const float* self_w2   = (const float*)d_in[base+7];
    const float* self_w3   = (const float*)d_in[base+8];
    const float* attn_fc_w = (const float*)d_in[base+9];
    const float* attn_fc_b = (const float*)d_in[base+10];
    const float* comp_fc_w = (const float*)d_in[base+11];
    const float* comp_fc_b = (const float*)d_in[base+12];
    const float* gate_fc_w = (const float*)d_in[base+13];
    const float* gate_fc_b = (const float*)d_in[base+14];
    const float* self_fc_w = (const float*)d_in[base+15];
    const float* self_fc_b = (const float*)d_in[base+16];
    float* out = (float*)d_out;

    float *opt_enc, *doc_enc, *logitOpt, *attnOpt, *X, *corr, *option;
    float *logitD, *kq, *attnD, *cow, *coattn, *fusion, *logitS, *attn2, *fusion2;
    float *rowq, *rowk, *rowkd;
    int *opt_mask, *doc_mask;
    cudaGetSymbolAddress((void**)&opt_enc,  g_opt_enc);
    cudaGetSymbolAddress((void**)&doc_enc,  g_doc_enc);
    cudaGetSymbolAddress((void**)&logitOpt, g_logitOpt);
    cudaGetSymbolAddress((void**)&attnOpt,  g_attnOpt);
    cudaGetSymbolAddress((void**)&X,        g_X);
    cudaGetSymbolAddress((void**)&corr,     g_corr);
    cudaGetSymbolAddress((void**)&option,   g_option);
    cudaGetSymbolAddress((void**)&logitD,   g_logitD);
    cudaGetSymbolAddress((void**)&kq,       g_kq);
    cudaGetSymbolAddress((void**)&attnD,    g_attnD);
    cudaGetSymbolAddress((void**)&cow,      g_cow);
    cudaGetSymbolAddress((void**)&coattn,   g_coattn);
    cudaGetSymbolAddress((void**)&fusion,   g_fusion);
    cudaGetSymbolAddress((void**)&logitS,   g_logitS);
    cudaGetSymbolAddress((void**)&attn2,    g_attn2);
    cudaGetSymbolAddress((void**)&fusion2,  g_fusion2);
    cudaGetSymbolAddress((void**)&rowq,     g_rowq);
    cudaGetSymbolAddress((void**)&rowk,     g_rowk);
    cudaGetSymbolAddress((void**)&rowkd,    g_rowkd);
    cudaGetSymbolAddress((void**)&opt_mask, g_opt_mask);
    cudaGetSymbolAddress((void**)&doc_mask, g_doc_mask);

    const int EW_BLOCKS = (MR * HD) / 256;   // 65536

    // 1) build encodings + masks
    k_build_opt<<<dim3(LO,  NRW), 256>>>(ll, am, fpw);
    k_build_doc<<<dim3(LDC, NRW), 256>>>(ll, am, fpw);

    // 2) opt-opt cross attention (192 pairs)
    k_rowdot<<<MR, 256>>>(opt_enc, opt_w1, rowq);
    k_rowdot<<<MR, 256>>>(opt_enc, opt_w2, rowk);
    k_gemm_nt<4><<<dim3(LO/128, LO/128, NPAIR), 256>>>(
        opt_enc, opt_enc, logitOpt, LO, LO, HD, 0,0,0,
        opt_w3, nullptr, rowq, rowk, opt_mask, opt_mask, 0,0, nullptr,nullptr, 1);
    k_row_softmax<<<dim3(LO, NPAIR), 256>>>(logitOpt, LO, opt_mask, opt_mask, 0,0,0, 1);
    k_gemm_nn<<<dim3(HD/128, LO/128, NPAIR), 256>>>(
        logitOpt, opt_enc, attnOpt, LO, HD, LO, 0,0,0, 1);

    // 3) comp FC (K = 7H)
    k_feats<<<EW_BLOCKS, 256>>>();
    k_gemm_nt<1><<<dim3(HD/128, MR/128, 1), 256>>>(
        X, comp_fc_w, corr, MR, HD, 7*HD, 0,0,0,
        nullptr, comp_fc_b, nullptr,nullptr,nullptr,nullptr, 0,0, nullptr,nullptr, 0);

    // 4) gate FC (K = 2H) with fused gate-combine epilogue -> option
    k_concat2<<<EW_BLOCKS, 256>>>();
    k_gemm_nt<3><<<dim3(HD/128, MR/128, 1), 256>>>(
        X, gate_fc_w, option, MR, HD, 2*HD, 0,0,0,
        nullptr, gate_fc_b, nullptr,nullptr,nullptr,nullptr, 0,0, opt_enc, corr, 0);

    // 5) doc attention (with co-attention)
    k_rowdot<<<MR, 256>>>(option, attn_w1, rowq);
    k_rowdot<<<NRW*LDC, 256>>>(doc_enc, attn_w2, rowkd);
    k_gemm_nt<4><<<dim3(LDC/128, LO/128, NRW), 256>>>(
        option, doc_enc, logitD, LO, LDC, HD,
        (long)LO*HD, (long)LDC*HD, (long)LO*LDC,
        attn_w3, nullptr, rowq, rowkd, opt_mask, doc_mask, LO, LDC, nullptr,nullptr, 0);
    k_col_softmax<<<dim3(LDC/256, NRW), 256>>>();                       // kq first
    k_row_softmax<<<dim3(LO, NRW), 256>>>(logitD, LDC, opt_mask, doc_mask,
        (long)LO*LDC, LO, LDC, 0);                                      // aw in place
    k_gemm_nn<<<dim3(HD/128, LO/128, NRW), 256>>>(
        logitD, doc_enc, attnD, LO, HD, LDC,
        (long)LO*LDC, (long)LDC*HD, (long)LO*HD, 0);
    k_gemm_nt<0><<<dim3(LO/128, LO/128, NRW), 256>>>(
        logitD, kq, cow, LO, LO, LDC,
        (long)LO*LDC, (long)LO*LDC, (long)LO*LO,
        nullptr, nullptr, nullptr,nullptr,nullptr,nullptr, 0,0, nullptr,nullptr, 0);
    k_gemm_nn<<<dim3(HD/128, LO/128, NRW), 256>>>(
        cow, option, coattn, LO, HD, LO,
        (long)LO*LO, (long)LO*HD, (long)LO*HD, 0);

    // 6) attn FC (K = 3H) -> fusion
    k_concat3<<<EW_BLOCKS, 256>>>();
    k_gemm_nt<1><<<dim3(HD/128, MR/128, 1), 256>>>(
        X, attn_fc_w, fusion, MR, HD, 3*HD, 0,0,0,
        nullptr, attn_fc_b, nullptr,nullptr,nullptr,nullptr, 0,0, nullptr,nullptr, 0);

    // 7) self attention
    k_rowdot<<<MR, 256>>>(fusion, self_w1, rowq);
    k_rowdot<<<MR, 256>>>(fusion, self_w2, rowk);
    k_gemm_nt<4><<<dim3(LO/128, LO/128, NRW), 256>>>(
        fusion, fusion, logitS, LO, LO, HD,
        (long)LO*HD, (long)LO*HD, (long)LO*LO,
        self_w3, nullptr, rowq, rowk, opt_mask, opt_mask, LO, LO, nullptr,nullptr, 0);
    k_row_softmax<<<dim3(LO, NRW), 256>>>(logitS, LO, opt_mask, opt_mask,
        (long)LO*LO, LO, LO, 0);
    k_gemm_nn<<<dim3(HD/128, LO/128, NRW), 256>>>(
        logitS, fusion, attn2, LO, HD, LO,
        (long)LO*LO, (long)LO*HD, (long)LO*HD, 0);

    // 8) self FC (K = 4H) -> fusion2
    k_concat4<<<EW_BLOCKS, 256>>>();
    k_gemm_nt<2><<<dim3(HD/128, MR/128, 1), 256>>>(
        X, self_fc_w, fusion2, MR, HD, 4*HD, 0,0,0,
        nullptr, self_fc_b, nullptr,nullptr,nullptr,nullptr, 0,0, nullptr,nullptr, 0);

    // 9) masked max over option positions
    k_final<<<dim3(HD/256, NRW), 256>>>(out);
}

// round 6
// speedup vs baseline: 1.0636x; 1.0636x over previous
#include <cuda_runtime.h>
#include <math.h>
#include <stdint.h>

#define HD    1024
#define NL4   4
#define SEQ   512
#define NRW   64
#define LO    256
#define LDC   512
#define NPAIR (NRW*3)
#define MR    (NRW*LO)
#define NEGV  -1e30f

// ---------------------------------------------------------------------------
// Static device scratch
// ---------------------------------------------------------------------------
__device__ float g_opt_enc[MR*HD];
__device__ int   g_opt_mask[MR];
__device__ float g_doc_enc[NRW*LDC*HD];
__device__ int   g_doc_mask[NRW*LDC];
__device__ float g_logitOpt[NPAIR*LO*LO];
__device__ float g_attnOpt[NPAIR*LO*HD];
__device__ float g_X[MR*7*HD];
__device__ float g_corr[MR*HD];
__device__ float g_option[MR*HD];
__device__ float g_logitD[NRW*LO*LDC];
__device__ float g_kq[NRW*LO*LDC];
__device__ float g_attnD[MR*HD];
__device__ float g_cow[NRW*LO*LO];
__device__ float g_coattn[MR*HD];
__device__ float g_fusion[MR*HD];
__device__ float g_logitS[NRW*LO*LO];
__device__ float g_attn2[MR*HD];
__device__ float g_fusion2[MR*HD];
__device__ float g_rowq[MR];
__device__ float g_rowk[MR];
__device__ float g_rowkd[NRW*LDC];

// ---------------------------------------------------------------------------
// Helpers
// ---------------------------------------------------------------------------
__device__ __forceinline__ int read_fp(const int* __restrict__ p, int n)
{
    return (p[1] == 0) ? p[2*n] : p[n];   // int64 vs int32 sniff (values 300..450)
}

__device__ __forceinline__ float tf32r(float x)
{
    uint32_t u;
    asm("cvt.rna.tf32.f32 %0, %1;" : "=r"(u) : "f"(x));
    return __uint_as_float(u);
}

__device__ __forceinline__ void mma_tf32(float* c, const uint32_t* a, const uint32_t* b)
{
    asm volatile(
        "mma.sync.aligned.m16n8k8.row.col.f32.tf32.tf32.f32 "
        "{%0,%1,%2,%3}, {%4,%5,%6,%7}, {%8,%9}, {%0,%1,%2,%3};"
        : "+f"(c[0]), "+f"(c[1]), "+f"(c[2]), "+f"(c[3])
        : "r"(a[0]), "r"(a[1]), "r"(a[2]), "r"(a[3]), "r"(b[0]), "r"(b[1]));
}

// ---------------------------------------------------------------------------
// Build kernels
// ---------------------------------------------------------------------------
__global__ void k_build_opt(const float* __restrict__ ll, const int* __restrict__ am,
                            const int* __restrict__ fpw)
{
    int o = blockIdx.x, n = blockIdx.y, t = threadIdx.x;
    int fp = read_fp(fpw, n);
    int idx = fp + o;
    int valid = (idx >= 0) && (idx < SEQ);
    int idxc = valid ? idx : (SEQ - 1);
    int m = valid && (am[n*SEQ + idxc] > 0);
    const float4* src = (const float4*)(ll + (size_t)(n*SEQ + idxc) * HD);
    float4* dst = (float4*)(g_opt_enc + (size_t)(n*LO + o) * HD);
    float4 v = m ? src[t] : make_float4(0.f,0.f,0.f,0.f);
    dst[t] = v;
    if (t == 0) g_opt_mask[n*LO + o] = m;
}

__global__ void k_build_doc(const float* __restrict__ ll, const int* __restrict__ am,
                            const int* __restrict__ fpw)
{
    int t0 = blockIdx.x, n = blockIdx.y, t = threadIdx.x;
    int fp = read_fp(fpw, n);
    int m = (t0 < fp) && (am[n*SEQ + t0] > 0);
    const float4* src = (const float4*)(ll + (size_t)(n*SEQ + t0) * HD);
    float4* dst = (float4*)(g_doc_enc + (size_t)(n*LDC + t0) * HD);
    float4 v = m ? src[t] : make_float4(0.f,0.f,0.f,0.f);
    dst[t] = v;
    if (t == 0) g_doc_mask[n*LDC + t0] = m;
}

__global__ void k_rowdot(const float* __restrict__ X, const float* __restrict__ w,
                         float* __restrict__ out)
{
    int r = blockIdx.x;
    const float* x = X + (size_t)r * HD;
    float s = 0.f;
    for (int i = threadIdx.x; i < HD; i += 256) s += x[i] * w[i];
    __shared__ float sh[256];
    sh[threadIdx.x] = s; __syncthreads();
    for (int st = 128; st > 0; st >>= 1) {
        if (threadIdx.x < st) sh[threadIdx.x] += sh[threadIdx.x + st];
        __syncthreads();
    }
    if (threadIdx.x == 0) out[r] = sh[0];
}

// ---------------------------------------------------------------------------
// fp32 SGEMMs (attention path), unchanged from the 18.1ms baseline
// ---------------------------------------------------------------------------
template<int EPI>   // 0=none 4=trilinear logits
__global__ __launch_bounds__(256) void k_gemm_nt(
    const float* __restrict__ A, const float* __restrict__ B, float* __restrict__ C,
    int M, int N, int K,
    long sA, long sB, long sC,
    const float* __restrict__ colScale,
    const float* __restrict__ ql, const float* __restrict__ kl,
    const int* __restrict__ mq, const int* __restrict__ mk,
    long sQl, long sKl,
    int pairMode)
{
    __shared__ float As[8][128];
    __shared__ float Bs[8][128];
    const int z = blockIdx.z;
    long offA, offB, offC, offQl, offKl;
    if (pairMode) {
        int n = z / 3, jj = z % 3;
        int b = n / NL4, i = n % NL4;
        int j = jj + (jj >= i ? 1 : 0);
        int mb = b * NL4 + j;
        offA = (long)n * LO * HD; offB = (long)mb * LO * HD;
        offC = (long)z * M * N;
        offQl = (long)n * LO; offKl = (long)mb * LO;
    } else {
        offA = z * sA; offB = z * sB; offC = z * sC;
        offQl = z * sQl; offKl = z * sKl;
    }
    const float* Ab = A + offA;
    const float* Bb = B + offB;
    const int tid = threadIdx.x;
    const int bm = blockIdx.y * 128, bn = blockIdx.x * 128;
    const int lr = tid >> 1, lc = (tid & 1) * 4;
    const int ty = tid >> 4, tx = tid & 15;
    float acc[8][8];
#pragma unroll
    for (int i = 0; i < 8; i++)
#pragma unroll
        for (int j = 0; j < 8; j++) acc[i][j] = 0.f;

    for (int k0 = 0; k0 < K; k0 += 8) {
        float4 av = *(const float4*)(Ab + (size_t)(bm + lr) * K + k0 + lc);
        float4 bv = *(const float4*)(Bb + (size_t)(bn + lr) * K + k0 + lc);
        if (EPI == 4) {
            bv.x *= colScale[k0 + lc];     bv.y *= colScale[k0 + lc + 1];
            bv.z *= colScale[k0 + lc + 2]; bv.w *= colScale[k0 + lc + 3];
        }
        As[lc][lr] = av.x; As[lc+1][lr] = av.y; As[lc+2][lr] = av.z; As[lc+3][lr] = av.w;
        Bs[lc][lr] = bv.x; Bs[lc+1][lr] = bv.y; Bs[lc+2][lr] = bv.z; Bs[lc+3][lr] = bv.w;
        __syncthreads();
#pragma unroll
        for (int kk = 0; kk < 8; kk++) {
            float a[8], b[8];
#pragma unroll
            for (int u = 0; u < 8; u++) { a[u] = As[kk][ty*8+u]; b[u] = Bs[kk][tx*8+u]; }
#pragma unroll
            for (int i = 0; i < 8; i++)
#pragma unroll
                for (int j = 0; j < 8; j++) acc[i][j] += a[i] * b[j];
        }
        __syncthreads();
    }
#pragma unroll
    for (int i = 0; i < 8; i++) {
        int m = bm + ty * 8 + i;
#pragma unroll
        for (int j = 0; j < 8; j++) {
            int nn = bn + tx * 8 + j;
            size_t ci = (size_t)offC + (size_t)m * N + nn;
            float v = acc[i][j];
            if (EPI == 0) C[ci] = v;
            else {
                v += ql[offQl + m] + kl[offKl + nn];
                C[ci] = (mq[offQl + m] && mk[offKl + nn]) ? v : NEGV;
            }
        }
    }
}

__global__ __launch_bounds__(256) void k_gemm_nn(
    const float* __restrict__ A, const float* __restrict__ B, float* __restrict__ C,
    int M, int N, int K, long sA, long sB, long sC, int pairMode)
{
    __shared__ float As[8][128];
    __shared__ float Bs[8][128];
    int z = blockIdx.z;
    long offA, offB, offC;
    if (pairMode) {
        int n = z / 3, jj = z % 3;
        int b = n / NL4, i = n % NL4;
        int j = jj + (jj >= i ? 1 : 0);
        int mb = b * NL4 + j;
        offA = (long)z * LO * LO; offB = (long)mb * LO * HD; offC = (long)z * LO * HD;
    } else { offA = z * sA; offB = z * sB; offC = z * sC; }
    const float* Ab = A + offA;
    const float* Bb = B + offB;
    int tid = threadIdx.x;
    int bm = blockIdx.y * 128, bn = blockIdx.x * 128;
    int lr = tid >> 1, lc = (tid & 1) * 4;
    int br = tid >> 5, bc = (tid & 31) * 4;
    int ty = tid >> 4, tx = tid & 15;
    float acc[8][8];
#pragma unroll
    for (int i = 0; i < 8; i++)
#pragma unroll
        for (int j = 0; j < 8; j++) acc[i][j] = 0.f;

    for (int k0 = 0; k0 < K; k0 += 8) {
        float4 av = *(const float4*)(Ab + (size_t)(bm + lr) * K + k0 + lc);
        As[lc][lr] = av.x; As[lc+1][lr] = av.y; As[lc+2][lr] = av.z; As[lc+3][lr] = av.w;
        float4 bv = *(const float4*)(Bb + (size_t)(k0 + br) * N + bn + bc);
        *(float4*)&Bs[br][bc] = bv;
        __syncthreads();
#pragma unroll
        for (int kk = 0; kk < 8; kk++) {
            float a[8], b[8];
#pragma unroll
            for (int u = 0; u < 8; u++) { a[u] = As[kk][ty*8+u]; b[u] = Bs[kk][tx*8+u]; }
#pragma unroll
            for (int i = 0; i < 8; i++)
#pragma unroll
                for (int j = 0; j < 8; j++) acc[i][j] += a[i] * b[j];
        }
        __syncthreads();
    }
#pragma unroll
    for (int i = 0; i < 8; i++) {
        int m = bm + ty * 8 + i;
#pragma unroll
        for (int j = 0; j < 8; j++) {
            int nn = bn + tx * 8 + j;
            C[(size_t)offC + (size_t)m * N + nn] = acc[i][j];
        }
    }
}

// ---------------------------------------------------------------------------
// 3xTF32 mma.sync FC GEMM: C[MR,HD] = act(X[MR,K] @ W[HD,K]^T + bias)
// BM=128, BN=128, BK=16, 8 warps (2m x 4n), 64x32 warp tiles,
// double-buffered smem, in-kernel hi/lo split (x = hi + lo, tf32 each):
// x*w ~= hi*hi' + hi*lo' + lo*hi'  (error ~2^-21, effectively fp32)
// EPI: 1=tanh(+bias) 2=relu(+bias) 3=sigmoid gate: C = E1*g + E2*(1-g)
// smem: [buf2][Ahi,Alo,Bhi,Blo][128 rows x 20 floats] = 81920 B
// ---------------------------------------------------------------------------
#define FC_SMEM (2*4*128*20*4)   // 81920

template<int EPI>
__global__ __launch_bounds__(256, 1) void k_fc_mma(
    const float* __restrict__ A, const float* __restrict__ Bw,
    float* __restrict__ C, int K,
    const float* __restrict__ bias,
    const float* __restrict__ E1, const float* __restrict__ E2)
{
    extern __shared__ float sm[];     // plane = 2560 floats; buf stride = 10240
    const int tid = threadIdx.x;
    const int lane = tid & 31, wid = tid >> 5;
    const int wm = wid & 1, wn = wid >> 1;
    const int g = lane >> 2, t = lane & 3;
    const int bm = blockIdx.y << 7, bn = blockIdx.x << 7;

    float acc[4][4][4];
#pragma unroll
    for (int i = 0; i < 4; i++)
#pragma unroll
        for (int q = 0; q < 4; q++)
#pragma unroll
            for (int c = 0; c < 4; c++) acc[i][q][c] = 0.f;

    // Producer: threads 0..127 own one A row, 128..255 one B row (16 k each).
    const int prow = tid & 127;
    const bool isA = tid < 128;
    const float* gsrc = isA ? (A  + (size_t)(bm + prow) * K)
                            : (Bw + (size_t)(bn + prow) * K);
    float4 st[4];

    auto fetch = [&](int ch) {
        const float* p = gsrc + (ch << 4);
#pragma unroll
        for (int q = 0; q < 4; q++) st[q] = *(const float4*)(p + (q << 2));
    };
    auto store_buf = [&](int buf) {
        float* d = sm + buf*10240 + (isA ? 0 : 5120) + prow*20;
#pragma unroll
        for (int q = 0; q < 4; q++) {
            float4 v = st[q], hi, lo;
            hi.x = tf32r(v.x); lo.x = tf32r(v.x - hi.x);
            hi.y = tf32r(v.y); lo.y = tf32r(v.y - hi.y);
            hi.z = tf32r(v.z); lo.z = tf32r(v.z - hi.z);
            hi.w = tf32r(v.w); lo.w = tf32r(v.w - hi.w);
            *(float4*)(d + (q << 2)) = hi;
            *(float4*)(d + 2560 + (q << 2)) = lo;
        }
    };

    const int T = K >> 4;
    fetch(0);
    store_buf(0);
    __syncthreads();

    for (int ch = 0; ch < T; ++ch) {
        const int buf = ch & 1;
        if (ch + 1 < T) fetch(ch + 1);

        const float* Ah = sm + buf*10240;
        const float* Al = Ah + 2560;
        const float* Bh = Ah + 5120;
        const float* Bl = Ah + 7680;
        const int ab = wm << 6, nb = wn << 5;

#pragma unroll
        for (int j = 0; j < 2; j++) {
            const int ko = (j << 3) + t;
            uint32_t ah[4][4], al[4][4], bh[4][2], bl[4][2];
#pragma unroll
            for (int i = 0; i < 4; i++) {
                int r0 = (ab + (i << 4) + g) * 20 + ko;
                ah[i][0] = __float_as_uint(Ah[r0]);
                ah[i][1] = __float_as_uint(Ah[r0 + 160]);
                ah[i][2] = __float_as_uint(Ah[r0 + 4]);
                ah[i][3] = __float_as_uint(Ah[r0 + 164]);
            }
#pragma unroll
            for (int q = 0; q < 4; q++) {
                int rb = (nb + (q << 3) + g) * 20 + ko;
                bh[q][0] = __float_as_uint(Bh[rb]);
                bh[q][1] = __float_as_uint(Bh[rb + 4]);
            }
#pragma unroll
            for (int i = 0; i < 4; i++)
#pragma unroll
                for (int q = 0; q < 4; q++) mma_tf32(acc[i][q], ah[i], bh[q]);
#pragma unroll
            for (int q = 0; q < 4; q++) {
                int rb = (nb + (q << 3) + g) * 20 + ko;
                bl[q][0] = __float_as_uint(Bl[rb]);
                bl[q][1] = __float_as_uint(Bl[rb + 4]);
            }
#pragma unroll
            for (int i = 0; i < 4; i++)
#pragma unroll
                for (int q = 0; q < 4; q++) mma_tf32(acc[i][q], ah[i], bl[q]);
#pragma unroll
            for (int i = 0; i < 4; i++) {
                int r0 = (ab + (i << 4) + g) * 20 + ko;
                al[i][0] = __float_as_uint(Al[r0]);
                al[i][1] = __float_as_uint(Al[r0 + 160]);
                al[i][2] = __float_as_uint(Al[r0 + 4]);
                al[i][3] = __float_as_uint(Al[r0 + 164]);
            }
#pragma unroll
            for (int i = 0; i < 4; i++)
#pragma unroll
                for (int q = 0; q < 4; q++) mma_tf32(acc[i][q], al[i], bh[q]);
        }
        __syncthreads();
        if (ch + 1 < T) store_buf(buf ^ 1);
        __syncthreads();
    }

    // Epilogue
#pragma unroll
    for (int i = 0; i < 4; i++) {
        int row0 = bm + (wm << 6) + (i << 4) + g;
#pragma unroll
        for (int q = 0; q < 4; q++) {
            int col = bn + (wn << 5) + (q << 3) + (t << 1);
            float b0 = bias[col], b1 = bias[col + 1];
#pragma unroll
            for (int h = 0; h < 2; h++) {
                int row = row0 + h * 8;
                float v0 = acc[i][q][h*2+0] + b0;
                float v1 = acc[i][q][h*2+1] + b1;
                size_t ci = (size_t)row * HD + col;
                float2 o;
                if (EPI == 1)      { o.x = tanhf(v0);        o.y = tanhf(v1); }
                else if (EPI == 2) { o.x = fmaxf(v0, 0.f);   o.y = fmaxf(v1, 0.f); }
                else {
                    float g0 = 1.f / (1.f + expf(-v0));
                    float g1 = 1.f / (1.f + expf(-v1));
                    o.x = E1[ci]   * g0 + E2[ci]   * (1.f - g0);
                    o.y = E1[ci+1] * g1 + E2[ci+1] * (1.f - g1);
                }
                *(float2*)(C + ci) = o;
            }
        }
    }
}

// ---------------------------------------------------------------------------
// Softmax kernels
// ---------------------------------------------------------------------------
__global__ void k_row_softmax(float* __restrict__ X, int Cdim,
    const int* __restrict__ mqb, const int* __restrict__ mkb,
    long sX, long sMq, long sMk, int pairMode)
{
    int z = blockIdx.y, row = blockIdx.x;
    long offX, offMq, offMk;
    if (pairMode) {
        int n = z / 3, jj = z % 3;
        int b = n / NL4, i = n % NL4;
        int j = jj + (jj >= i ? 1 : 0);
        int mb = b * NL4 + j;
        offX = (long)z * LO * LO; offMq = (long)n * LO; offMk = (long)mb * LO;
    } else { offX = z * sX; offMq = z * sMq; offMk = z * sMk; }
    float* x = X + offX + (long)row * Cdim;
    const int* mk = mkb + offMk;
    int qm = mqb[offMq + row];
    int tid = threadIdx.x;
    __shared__ float sh[256];
    float mx = -3.4e38f;
    for (int c = tid; c < Cdim; c += 256) mx = fmaxf(mx, x[c]);
    sh[tid] = mx; __syncthreads();
    for (int s = 128; s > 0; s >>= 1) {
        if (tid < s) sh[tid] = fmaxf(sh[tid], sh[tid + s]);
        __syncthreads();
    }
    mx = sh[0]; __syncthreads();
    float sum = 0.f;
    for (int c = tid; c < Cdim; c += 256) sum += expf(x[c] - mx);
    sh[tid] = sum; __syncthreads();
    for (int s = 128; s > 0; s >>= 1) {
        if (tid < s) sh[tid] += sh[tid + s];
        __syncthreads();
    }
    float inv = 1.f / sh[0];
    for (int c = tid; c < Cdim; c += 256) {
        float e = expf(x[c] - mx);
        x[c] = (qm && mk[c]) ? e * inv : 0.f;
    }
}

__global__ void k_col_softmax()
{
    int n = blockIdx.y;
    int t = blockIdx.x * 256 + threadIdx.x;
    const float* x = g_logitD + (size_t)n * LO * LDC;
    float mx = -3.4e38f;
    for (int o = 0; o < LO; o++) mx = fmaxf(mx, x[(size_t)o * LDC + t]);
    float sum = 0.f;
    for (int o = 0; o < LO; o++) sum += expf(x[(size_t)o * LDC + t] - mx);
    float inv = 1.f / sum;
    int km = g_doc_mask[n*LDC + t];
    float* y = g_kq + (size_t)n * LO * LDC;
    for (int o = 0; o < LO; o++) {
        float e = expf(x[(size_t)o * LDC + t] - mx);
        y[(size_t)o * LDC + t] = (km && g_opt_mask[n*LO + o]) ? e * inv : 0.f;
    }
}

// ---------------------------------------------------------------------------
// Concat builders (plain fp32 — precision handled inside k_fc_mma) + final max
// ---------------------------------------------------------------------------
__global__ void k_feats()
{
    size_t idx = (size_t)blockIdx.x * 256 + threadIdx.x;
    size_t r = idx >> 10;
    int h = (int)(idx & 1023);
    int n = (int)(r >> 8);
    int o = (int)(r & 255);
    float cur = g_opt_enc[idx];
    float* xr = g_X + r * (7*HD);
    xr[h] = cur;
#pragma unroll
    for (int jj = 0; jj < 3; jj++) {
        float a = g_attnOpt[(((size_t)(n*3 + jj) * LO + o) << 10) + h];
        xr[(1 + 2*jj)*HD + h] = cur * a;
        xr[(2 + 2*jj)*HD + h] = cur - a;
    }
}

__global__ void k_concat2()
{
    size_t idx = (size_t)blockIdx.x * 256 + threadIdx.x;
    size_t r = idx >> 10;
    int h = (int)(idx & 1023);
    float* xr = g_X + r * (2*HD);
    xr[h] = g_opt_enc[idx];
    xr[HD + h] = g_corr[idx];
}

__global__ void k_concat3()
{
    size_t idx = (size_t)blockIdx.x * 256 + threadIdx.x;
    size_t r = idx >> 10;
    int h = (int)(idx & 1023);
    float* xr = g_X + r * (3*HD);
    xr[h] = g_option[idx];
    xr[HD + h] = g_attnD[idx];
    xr[2*HD + h] = g_coattn[idx];
}

__global__ void k_concat4()
{
    size_t idx = (size_t)blockIdx.x * 256 + threadIdx.x;
    size_t r = idx >> 10;
    int h = (int)(idx & 1023);
    float f = g_fusion[idx];
    float a = g_attn2[idx];
    float* xr = g_X + r * (4*HD);
    xr[h] = f;
    xr[HD + h] = a;
    xr[2*HD + h] = f * a;
    xr[3*HD + h] = f - a;
}

__global__ void k_final(float* __restrict__ out)
{
    int n = blockIdx.y;
    int h = blockIdx.x * 256 + threadIdx.x;
    float mx = NEGV;
    for (int o = 0; o < LO; o++) {
        if (g_opt_mask[n*LO + o])
            mx = fmaxf(mx, g_fusion2[((size_t)(n*LO + o) << 10) + h]);
    }
    out[(size_t)n * HD + h] = mx;
}

// ---------------------------------------------------------------------------
// Launch
// ---------------------------------------------------------------------------
extern "C" void kernel_launch(void* const* d_in, const int* in_sizes, int n_in,
                              void* d_out, int out_size)
{
    const float* ll  = (const float*)d_in[0];
    const int*   am  = (const int*)d_in[1];
    const int*   fpw = (const int*)d_in[2];
    int base = (in_sizes[3] <= 8) ? 4 : 3;
    const float* attn_w1   = (const float*)d_in[base+0];
    const float* attn_w2   = (const float*)d_in[base+1];
    const float* attn_w3   = (const float*)d_in[base+2];
    const float* opt_w1    = (const float*)d_in[base+3];
    const float* opt_w2    = (const float*)d_in[base+4];
    const float* opt_w3    = (const float*)d_in[base+5];
    const float* self_w1   = (const float*)d_in[base+6];
    const float* self_w2   = (const float*)d_in[base+7];
    const float* self_w3   = (const float*)d_in[base+8];
    const float* attn_fc_w = (const float*)d_in[base+9];
    const float* attn_fc_b = (const float*)d_in[base+10];
    const float* comp_fc_w = (const float*)d_in[base+11];
    const float* comp_fc_b = (const float*)d_in[base+12];
    const float* gate_fc_w = (const float*)d_in[base+13];
    const float* gate_fc_b = (const float*)d_in[base+14];
    const float* self_fc_w = (const float*)d_in[base+15];
    const float* self_fc_b = (const float*)d_in[base+16];
    float* out = (float*)d_out;

    float *opt_enc, *doc_enc, *logitOpt, *attnOpt, *X, *corr, *option;
    float *logitD, *kq, *attnD, *cow, *coattn, *fusion, *logitS, *attn2, *fusion2;
    float *rowq, *rowk, *rowkd;
    int *opt_mask, *doc_mask;
    cudaGetSymbolAddress((void**)&opt_enc,  g_opt_enc);
    cudaGetSymbolAddress((void**)&doc_enc,  g_doc_enc);
    cudaGetSymbolAddress((void**)&logitOpt, g_logitOpt);
    cudaGetSymbolAddress((void**)&attnOpt,  g_attnOpt);
    cudaGetSymbolAddress((void**)&X,        g_X);
    cudaGetSymbolAddress((void**)&corr,     g_corr);
    cudaGetSymbolAddress((void**)&option,   g_option);
    cudaGetSymbolAddress((void**)&logitD,   g_logitD);
    cudaGetSymbolAddress((void**)&kq,       g_kq);
    cudaGetSymbolAddress((void**)&attnD,    g_attnD);
    cudaGetSymbolAddress((void**)&cow,      g_cow);
    cudaGetSymbolAddress((void**)&coattn,   g_coattn);
    cudaGetSymbolAddress((void**)&fusion,   g_fusion);
    cudaGetSymbolAddress((void**)&logitS,   g_logitS);
    cudaGetSymbolAddress((void**)&attn2,    g_attn2);
    cudaGetSymbolAddress((void**)&fusion2,  g_fusion2);
    cudaGetSymbolAddress((void**)&rowq,     g_rowq);
    cudaGetSymbolAddress((void**)&rowk,     g_rowk);
    cudaGetSymbolAddress((void**)&rowkd,    g_rowkd);
    cudaGetSymbolAddress((void**)&opt_mask, g_opt_mask);
    cudaGetSymbolAddress((void**)&doc_mask, g_doc_mask);

    cudaFuncSetAttribute(k_fc_mma<1>, cudaFuncAttributeMaxDynamicSharedMemorySize, FC_SMEM);
    cudaFuncSetAttribute(k_fc_mma<2>, cudaFuncAttributeMaxDynamicSharedMemorySize, FC_SMEM);
    cudaFuncSetAttribute(k_fc_mma<3>, cudaFuncAttributeMaxDynamicSharedMemorySize, FC_SMEM);

    const int EW_BLOCKS = (MR * HD) / 256;   // 65536
    const dim3 FC_GRID(HD/128, MR/128);      // 8 x 128

    // 1) build encodings + masks
    k_build_opt<<<dim3(LO,  NRW), 256>>>(ll, am, fpw);
    k_build_doc<<<dim3(LDC, NRW), 256>>>(ll, am, fpw);

    // 2) opt-opt cross attention (192 pairs)
    k_rowdot<<<MR, 256>>>(opt_enc, opt_w1, rowq);
    k_rowdot<<<MR, 256>>>(opt_enc, opt_w2, rowk);
    k_gemm_nt<4><<<dim3(LO/128, LO/128, NPAIR), 256>>>(
        opt_enc, opt_enc, logitOpt, LO, LO, HD, 0,0,0,
        opt_w3, rowq, rowk, opt_mask, opt_mask, 0,0, 1);
    k_row_softmax<<<dim3(LO, NPAIR), 256>>>(logitOpt, LO, opt_mask, opt_mask, 0,0,0, 1);
    k_gemm_nn<<<dim3(HD/128, LO/128, NPAIR), 256>>>(
        logitOpt, opt_enc, attnOpt, LO, HD, LO, 0,0,0, 1);

    // 3) comp FC (K = 7H) via 3xTF32 tensor path
    k_feats<<<EW_BLOCKS, 256>>>();
    k_fc_mma<1><<<FC_GRID, 256, FC_SMEM>>>(X, comp_fc_w, corr, 7*HD, comp_fc_b, nullptr, nullptr);

    // 4) gate FC (K = 2H) with fused gate-combine -> option
    k_concat2<<<EW_BLOCKS, 256>>>();
    k_fc_mma<3><<<FC_GRID, 256, FC_SMEM>>>(X, gate_fc_w, option, 2*HD, gate_fc_b, opt_enc, corr);

    // 5) doc attention (with co-attention)
    k_rowdot<<<MR, 256>>>(option, attn_w1, rowq);
    k_rowdot<<<NRW*LDC, 256>>>(doc_enc, attn_w2, rowkd);
    k_gemm_nt<4><<<dim3(LDC/128, LO/128, NRW), 256>>>(
        option, doc_enc, logitD, LO, LDC, HD,
        (long)LO*HD, (long)LDC*HD, (long)LO*LDC,
        attn_w3, rowq, rowkd, opt_mask, doc_mask, LO, LDC, 0);
    k_col_softmax<<<dim3(LDC/256, NRW), 256>>>();
    k_row_softmax<<<dim3(LO, NRW), 256>>>(logitD, LDC, opt_mask, doc_mask,
        (long)LO*LDC, LO, LDC, 0);
    k_gemm_nn<<<dim3(HD/128, LO/128, NRW), 256>>>(
        logitD, doc_enc, attnD, LO, HD, LDC,
        (long)LO*LDC, (long)LDC*HD, (long)LO*HD, 0);
    k_gemm_nt<0><<<dim3(LO/128, LO/128, NRW), 256>>>(
        logitD, kq, cow, LO, LO, LDC,
        (long)LO*LDC, (long)LO*LDC, (long)LO*LO,
        nullptr, nullptr, nullptr, nullptr, nullptr, 0,0, 0);
    k_gemm_nn<<<dim3(HD/128, LO/128, NRW), 256>>>(
        cow, option, coattn, LO, HD, LO,
        (long)LO*LO, (long)LO*HD, (long)LO*HD, 0);

    // 6) attn FC (K = 3H) -> fusion
    k_concat3<<<EW_BLOCKS, 256>>>();
    k_fc_mma<1><<<FC_GRID, 256, FC_SMEM>>>(X, attn_fc_w, fusion, 3*HD, attn_fc_b, nullptr, nullptr);

    // 7) self attention
    k_rowdot<<<MR, 256>>>(fusion, self_w1, rowq);
    k_rowdot<<<MR, 256>>>(fusion, self_w2, rowk);
    k_gemm_nt<4><<<dim3(LO/128, LO/128, NRW), 256>>>(
        fusion, fusion, logitS, LO, LO, HD,
        (long)LO*HD, (long)LO*HD, (long)LO*LO,
        self_w3, rowq, rowk, opt_mask, opt_mask, LO, LO, 0);
    k_row_softmax<<<dim3(LO, NRW), 256>>>(logitS, LO, opt_mask, opt_mask,
        (long)LO*LO, LO, LO, 0);
    k_gemm_nn<<<dim3(HD/128, LO/128, NRW), 256>>>(
        logitS, fusion, attn2, LO, HD, LO,
        (long)LO*LO, (long)LO*HD, (long)LO*HD, 0);

    // 8) self FC (K = 4H) -> fusion2
    k_concat4<<<EW_BLOCKS, 256>>>();
    k_fc_mma<2><<<FC_GRID, 256, FC_SMEM>>>(X, self_fc_w, fusion2, 4*HD, self_fc_b, nullptr, nullptr);

    // 9) masked max over option positions
    k_final<<<dim3(HD/256, NRW), 256>>>(out);
}

// round 7
// speedup vs baseline: 1.3389x; 1.2588x over previous
#include <cuda_runtime.h>
#include <cuda_fp16.h>
#include <math.h>
#include <stdint.h>

#define HD    1024
#define NL4   4
#define SEQ   512
#define NRW   64
#define LO    256
#define LDC   512
#define NPAIR (NRW*3)
#define MR    (NRW*LO)
#define NEGV  -1e30f

// ---------------------------------------------------------------------------
// Static device scratch
// ---------------------------------------------------------------------------
__device__ float g_opt_enc[MR*HD];
__device__ int   g_opt_mask[MR];
__device__ float g_doc_enc[NRW*LDC*HD];
__device__ int   g_doc_mask[NRW*LDC];
__device__ float g_logitOpt[NPAIR*LO*LO];
__device__ float g_attnOpt[NPAIR*LO*HD];
__device__ float g_X[MR*7*HD];
__device__ float g_corr[MR*HD];
__device__ float g_option[MR*HD];
__device__ float g_logitD[NRW*LO*LDC];
__device__ float g_kq[NRW*LO*LDC];
__device__ float g_attnD[MR*HD];
__device__ float g_cow[NRW*LO*LO];
__device__ float g_coattn[MR*HD];
__device__ float g_fusion[MR*HD];
__device__ float g_logitS[NRW*LO*LO];
__device__ float g_attn2[MR*HD];
__device__ float g_fusion2[MR*HD];
__device__ float g_rowq[MR];
__device__ float g_rowk[MR];
__device__ float g_rowkd[NRW*LDC];

// ---------------------------------------------------------------------------
// Helpers
// ---------------------------------------------------------------------------
__device__ __forceinline__ int read_fp(const int* __restrict__ p, int n)
{
    return (p[1] == 0) ? p[2*n] : p[n];   // int64 vs int32 sniff (values 300..450)
}

__device__ __forceinline__ void mma_f16(float* c, const uint32_t* a, const uint32_t* b)
{
    asm volatile(
        "mma.sync.aligned.m16n8k16.row.col.f32.f16.f16.f32 "
        "{%0,%1,%2,%3}, {%4,%5,%6,%7}, {%8,%9}, {%0,%1,%2,%3};"
        : "+f"(c[0]), "+f"(c[1]), "+f"(c[2]), "+f"(c[3])
        : "r"(a[0]), "r"(a[1]), "r"(a[2]), "r"(a[3]), "r"(b[0]), "r"(b[1]));
}

// ---------------------------------------------------------------------------
// Build kernels
// ---------------------------------------------------------------------------
__global__ void k_build_opt(const float* __restrict__ ll, const int* __restrict__ am,
                            const int* __restrict__ fpw)
{
    int o = blockIdx.x, n = blockIdx.y, t = threadIdx.x;
    int fp = read_fp(fpw, n);
    int idx = fp + o;
    int valid = (idx >= 0) && (idx < SEQ);
    int idxc = valid ? idx : (SEQ - 1);
    int m = valid && (am[n*SEQ + idxc] > 0);
    const float4* src = (const float4*)(ll + (size_t)(n*SEQ + idxc) * HD);
    float4* dst = (float4*)(g_opt_enc + (size_t)(n*LO + o) * HD);
    float4 v = m ? src[t] : make_float4(0.f,0.f,0.f,0.f);
    dst[t] = v;
    if (t == 0) g_opt_mask[n*LO + o] = m;
}

__global__ void k_build_doc(const float* __restrict__ ll, const int* __restrict__ am,
                            const int* __restrict__ fpw)
{
    int t0 = blockIdx.x, n = blockIdx.y, t = threadIdx.x;
    int fp = read_fp(fpw, n);
    int m = (t0 < fp) && (am[n*SEQ + t0] > 0);
    const float4* src = (const float4*)(ll + (size_t)(n*SEQ + t0) * HD);
    float4* dst = (float4*)(g_doc_enc + (size_t)(n*LDC + t0) * HD);
    float4 v = m ? src[t] : make_float4(0.f,0.f,0.f,0.f);
    dst[t] = v;
    if (t == 0) g_doc_mask[n*LDC + t0] = m;
}

__global__ void k_rowdot(const float* __restrict__ X, const float* __restrict__ w,
                         float* __restrict__ out)
{
    int r = blockIdx.x;
    const float* x = X + (size_t)r * HD;
    float s = 0.f;
    for (int i = threadIdx.x; i < HD; i += 256) s += x[i] * w[i];
    __shared__ float sh[256];
    sh[threadIdx.x] = s; __syncthreads();
    for (int st = 128; st > 0; st >>= 1) {
        if (threadIdx.x < st) sh[threadIdx.x] += sh[threadIdx.x + st];
        __syncthreads();
    }
    if (threadIdx.x == 0) out[r] = sh[0];
}

// ---------------------------------------------------------------------------
// fp32 SGEMMs (attention path)
// ---------------------------------------------------------------------------
template<int EPI>   // 0=none 4=trilinear logits
__global__ __launch_bounds__(256) void k_gemm_nt(
    const float* __restrict__ A, const float* __restrict__ B, float* __restrict__ C,
    int M, int N, int K,
    long sA, long sB, long sC,
    const float* __restrict__ colScale,
    const float* __restrict__ ql, const float* __restrict__ kl,
    const int* __restrict__ mq, const int* __restrict__ mk,
    long sQl, long sKl,
    int pairMode)
{
    __shared__ float As[8][128];
    __shared__ float Bs[8][128];
    const int z = blockIdx.z;
    long offA, offB, offC, offQl, offKl;
    if (pairMode) {
        int n = z / 3, jj = z % 3;
        int b = n / NL4, i = n % NL4;
        int j = jj + (jj >= i ? 1 : 0);
        int mb = b * NL4 + j;
        offA = (long)n * LO * HD; offB = (long)mb * LO * HD;
        offC = (long)z * M * N;
        offQl = (long)n * LO; offKl = (long)mb * LO;
    } else {
        offA = z * sA; offB = z * sB; offC = z * sC;
        offQl = z * sQl; offKl = z * sKl;
    }
    const float* Ab = A + offA;
    const float* Bb = B + offB;
    const int tid = threadIdx.x;
    const int bm = blockIdx.y * 128, bn = blockIdx.x * 128;
    const int lr = tid >> 1, lc = (tid & 1) * 4;
    const int ty = tid >> 4, tx = tid & 15;
    float acc[8][8];
#pragma unroll
    for (int i = 0; i < 8; i++)
#pragma unroll
        for (int j = 0; j < 8; j++) acc[i][j] = 0.f;

    for (int k0 = 0; k0 < K; k0 += 8) {
        float4 av = *(const float4*)(Ab + (size_t)(bm + lr) * K + k0 + lc);
        float4 bv = *(const float4*)(Bb + (size_t)(bn + lr) * K + k0 + lc);
        if (EPI == 4) {
            bv.x *= colScale[k0 + lc];     bv.y *= colScale[k0 + lc + 1];
            bv.z *= colScale[k0 + lc + 2]; bv.w *= colScale[k0 + lc + 3];
        }
        As[lc][lr] = av.x; As[lc+1][lr] = av.y; As[lc+2][lr] = av.z; As[lc+3][lr] = av.w;
        Bs[lc][lr] = bv.x; Bs[lc+1][lr] = bv.y; Bs[lc+2][lr] = bv.z; Bs[lc+3][lr] = bv.w;
        __syncthreads();
#pragma unroll
        for (int kk = 0; kk < 8; kk++) {
            float a[8], b[8];
#pragma unroll
            for (int u = 0; u < 8; u++) { a[u] = As[kk][ty*8+u]; b[u] = Bs[kk][tx*8+u]; }
#pragma unroll
            for (int i = 0; i < 8; i++)
#pragma unroll
                for (int j = 0; j < 8; j++) acc[i][j] += a[i] * b[j];
        }
        __syncthreads();
    }
#pragma unroll
    for (int i = 0; i < 8; i++) {
        int m = bm + ty * 8 + i;
#pragma unroll
        for (int j = 0; j < 8; j++) {
            int nn = bn + tx * 8 + j;
            size_t ci = (size_t)offC + (size_t)m * N + nn;
            float v = acc[i][j];
            if (EPI == 0) C[ci] = v;
            else {
                v += ql[offQl + m] + kl[offKl + nn];
                C[ci] = (mq[offQl + m] && mk[offKl + nn]) ? v : NEGV;
            }
        }
    }
}

__global__ __launch_bounds__(256) void k_gemm_nn(
    const float* __restrict__ A, const float* __restrict__ B, float* __restrict__ C,
    int M, int N, int K, long sA, long sB, long sC, int pairMode)
{
    __shared__ float As[8][128];
    __shared__ float Bs[8][128];
    int z = blockIdx.z;
    long offA, offB, offC;
    if (pairMode) {
        int n = z / 3, jj = z % 3;
        int b = n / NL4, i = n % NL4;
        int j = jj + (jj >= i ? 1 : 0);
        int mb = b * NL4 + j;
        offA = (long)z * LO * LO; offB = (long)mb * LO * HD; offC = (long)z * LO * HD;
    } else { offA = z * sA; offB = z * sB; offC = z * sC; }
    const float* Ab = A + offA;
    const float* Bb = B + offB;
    int tid = threadIdx.x;
    int bm = blockIdx.y * 128, bn = blockIdx.x * 128;
    int lr = tid >> 1, lc = (tid & 1) * 4;
    int br = tid >> 5, bc = (tid & 31) * 4;
    int ty = tid >> 4, tx = tid & 15;
    float acc[8][8];
#pragma unroll
    for (int i = 0; i < 8; i++)
#pragma unroll
        for (int j = 0; j < 8; j++) acc[i][j] = 0.f;

    for (int k0 = 0; k0 < K; k0 += 8) {
        float4 av = *(const float4*)(Ab + (size_t)(bm + lr) * K + k0 + lc);
        As[lc][lr] = av.x; As[lc+1][lr] = av.y; As[lc+2][lr] = av.z; As[lc+3][lr] = av.w;
        float4 bv = *(const float4*)(Bb + (size_t)(k0 + br) * N + bn + bc);
        *(float4*)&Bs[br][bc] = bv;
        __syncthreads();
#pragma unroll
        for (int kk = 0; kk < 8; kk++) {
            float a[8], b[8];
#pragma unroll
            for (int u = 0; u < 8; u++) { a[u] = As[kk][ty*8+u]; b[u] = Bs[kk][tx*8+u]; }
#pragma unroll
            for (int i = 0; i < 8; i++)
#pragma unroll
                for (int j = 0; j < 8; j++) acc[i][j] += a[i] * b[j];
        }
        __syncthreads();
    }
#pragma unroll
    for (int i = 0; i < 8; i++) {
        int m = bm + ty * 8 + i;
#pragma unroll
        for (int j = 0; j < 8; j++) {
            int nn = bn + tx * 8 + j;
            C[(size_t)offC + (size_t)m * N + nn] = acc[i][j];
        }
    }
}

// ---------------------------------------------------------------------------
// 3xFP16 mma.sync FC GEMM: C[MR,HD] = act(X[MR,K] @ W[HD,K]^T + bias)
// x = hi + lo (fp16 each, ~22 mantissa bits combined);
// x*w ~= hi*hi' + hi*lo' + lo*hi'  (error ~2^-21 -> effectively fp32)
// BM=BN=128, BK=16, 8 warps (2m x 4n), 64x32 warp tiles, m16n8k16 HMMA.
// smem planes [k-pair t][row r] of half2, pair stride 544B:
//   frag LDS banks = (8t + g) mod 32 -> conflict-free; producer STS coalesced.
// EPI: 1=tanh(+bias) 2=relu(+bias) 3=sigmoid gate: C = E1*g + E2*(1-g)
// ---------------------------------------------------------------------------
#define PT    544                  // bytes between k-pair planes' rows
#define PLANE (8*PT)               // 4352 B (8 k-pairs x 128 rows x half2)
#define BUFB  (4*PLANE)            // Ahi, Alo, Bhi, Blo

template<int EPI>
__global__ __launch_bounds__(256, 1) void k_fc_mma(
    const float* __restrict__ A, const float* __restrict__ Bw,
    float* __restrict__ C, int K,
    const float* __restrict__ bias,
    const float* __restrict__ E1, const float* __restrict__ E2)
{
    __shared__ __align__(16) char sm[2*BUFB];   // 34816 B
    const int tid = threadIdx.x;
    const int lane = tid & 31, wid = tid >> 5;
    const int wm = wid & 1, wn = wid >> 1;
    const int g = lane >> 2, t = lane & 3;
    const int bm = blockIdx.y << 7, bn = blockIdx.x << 7;

    float acc[4][4][4];
#pragma unroll
    for (int i = 0; i < 4; i++)
#pragma unroll
        for (int q = 0; q < 4; q++)
#pragma unroll
            for (int c = 0; c < 4; c++) acc[i][q][c] = 0.f;

    // Producer: threads 0..127 own one A row, 128..255 one B row (16 k each).
    const int prow = tid & 127;
    const bool isA = tid < 128;
    const float* gsrc = isA ? (A  + (size_t)(bm + prow) * K)
                            : (Bw + (size_t)(bn + prow) * K);
    float4 st[4];

    auto fetch = [&](int ch) {
        const float* p = gsrc + (ch << 4);
#pragma unroll
        for (int q = 0; q < 4; q++) st[q] = *(const float4*)(p + (q << 2));
    };
    auto store_buf = [&](int buf) {
        char* d = sm + buf*BUFB + (isA ? 0 : 2*PLANE) + prow*4;
        const float* v = (const float*)st;
#pragma unroll
        for (int tt = 0; tt < 8; ++tt) {
            float x0 = v[2*tt], x1 = v[2*tt + 1];
            __half2 h2 = __floats2half2_rn(x0, x1);
            float l0 = x0 - __half2float(__low2half(h2));
            float l1 = x1 - __half2float(__high2half(h2));
            __half2 l2 = __floats2half2_rn(l0, l1);
            *(__half2*)(d + tt*PT) = h2;            // hi plane
            *(__half2*)(d + PLANE + tt*PT) = l2;    // lo plane
        }
    };

    const int T = K >> 4;
    fetch(0);
    store_buf(0);
    __syncthreads();

    for (int ch = 0; ch < T; ++ch) {
        const int buf = ch & 1;
        if (ch + 1 < T) fetch(ch + 1);

        const char* Ah = sm + buf*BUFB;
        const char* Al = Ah + PLANE;
        const char* Bh = Ah + 2*PLANE;
        const char* Bl = Ah + 3*PLANE;
        const int rA = (wm << 6) + g;
        const int rB = (wn << 5) + g;

        uint32_t ah[4][4], al[4][4], bh[4][2], bl[4][2];
#pragma unroll
        for (int i = 0; i < 4; i++) {
            const char* p = Ah + t*PT + (rA + (i << 4)) * 4;
            ah[i][0] = *(const uint32_t*)p;
            ah[i][1] = *(const uint32_t*)(p + 32);          // row + 8
            ah[i][2] = *(const uint32_t*)(p + 4*PT);        // k-pair t+4
            ah[i][3] = *(const uint32_t*)(p + 4*PT + 32);
        }
#pragma unroll
        for (int q = 0; q < 4; q++) {
            const char* p = Bh + t*PT + (rB + (q << 3)) * 4;
            bh[q][0] = *(const uint32_t*)p;
            bh[q][1] = *(const uint32_t*)(p + 4*PT);
        }
#pragma unroll
        for (int i = 0; i < 4; i++)
#pragma unroll
            for (int q = 0; q < 4; q++) mma_f16(acc[i][q], ah[i], bh[q]);
#pragma unroll
        for (int q = 0; q < 4; q++) {
            const char* p = Bl + t*PT + (rB + (q << 3)) * 4;
            bl[q][0] = *(const uint32_t*)p;
            bl[q][1] = *(const uint32_t*)(p + 4*PT);
        }
#pragma unroll
        for (int i = 0; i < 4; i++)
#pragma unroll
            for (int q = 0; q < 4; q++) mma_f16(acc[i][q], ah[i], bl[q]);
#pragma unroll
        for (int i = 0; i < 4; i++) {
            const char* p = Al + t*PT + (rA + (i << 4)) * 4;
            al[i][0] = *(const uint32_t*)p;
            al[i][1] = *(const uint32_t*)(p + 32);
            al[i][2] = *(const uint32_t*)(p + 4*PT);
            al[i][3] = *(const uint32_t*)(p + 4*PT + 32);
        }
#pragma unroll
        for (int i = 0; i < 4; i++)
#pragma unroll
            for (int q = 0; q < 4; q++) mma_f16(acc[i][q], al[i], bh[q]);

        __syncthreads();
        if (ch + 1 < T) store_buf(buf ^ 1);
        __syncthreads();
    }

    // Epilogue
#pragma unroll
    for (int i = 0; i < 4; i++) {
        int row0 = bm + (wm << 6) + (i << 4) + g;
#pragma unroll
        for (int q = 0; q < 4; q++) {
            int col = bn + (wn << 5) + (q << 3) + (t << 1);
            float b0 = bias[col], b1 = bias[col + 1];
#pragma unroll
            for (int h = 0; h < 2; h++) {
                int row = row0 + h * 8;
                float v0 = acc[i][q][h*2+0] + b0;
                float v1 = acc[i][q][h*2+1] + b1;
                size_t ci = (size_t)row * HD + col;
                float2 o;
                if (EPI == 1)      { o.x = tanhf(v0);        o.y = tanhf(v1); }
                else if (EPI == 2) { o.x = fmaxf(v0, 0.f);   o.y = fmaxf(v1, 0.f); }
                else {
                    float g0 = 1.f / (1.f + expf(-v0));
                    float g1 = 1.f / (1.f + expf(-v1));
                    o.x = E1[ci]   * g0 + E2[ci]   * (1.f - g0);
                    o.y = E1[ci+1] * g1 + E2[ci+1] * (1.f - g1);
                }
                *(float2*)(C + ci) = o;
            }
        }
    }
}

// ---------------------------------------------------------------------------
// Softmax kernels
// ---------------------------------------------------------------------------
__global__ void k_row_softmax(float* __restrict__ X, int Cdim,
    const int* __restrict__ mqb, const int* __restrict__ mkb,
    long sX, long sMq, long sMk, int pairMode)
{
    int z = blockIdx.y, row = blockIdx.x;
    long offX, offMq, offMk;
    if (pairMode) {
        int n = z / 3, jj = z % 3;
        int b = n / NL4, i = n % NL4;
        int j = jj + (jj >= i ? 1 : 0);
        int mb = b * NL4 + j;
        offX = (long)z * LO * LO; offMq = (long)n * LO; offMk = (long)mb * LO;
    } else { offX = z * sX; offMq = z * sMq; offMk = z * sMk; }
    float* x = X + offX + (long)row * Cdim;
    const int* mk = mkb + offMk;
    int qm = mqb[offMq + row];
    int tid = threadIdx.x;
    __shared__ float sh[256];
    float mx = -3.4e38f;
    for (int c = tid; c < Cdim; c += 256) mx = fmaxf(mx, x[c]);
    sh[tid] = mx; __syncthreads();
    for (int s = 128; s > 0; s >>= 1) {
        if (tid < s) sh[tid] = fmaxf(sh[tid], sh[tid + s]);
        __syncthreads();
    }
    mx = sh[0]; __syncthreads();
    float sum = 0.f;
    for (int c = tid; c < Cdim; c += 256) sum += expf(x[c] - mx);
    sh[tid] = sum; __syncthreads();
    for (int s = 128; s > 0; s >>= 1) {
        if (tid < s) sh[tid] += sh[tid + s];
        __syncthreads();
    }
    float inv = 1.f / sh[0];
    for (int c = tid; c < Cdim; c += 256) {
        float e = expf(x[c] - mx);
        x[c] = (qm && mk[c]) ? e * inv : 0.f;
    }
}

__global__ void k_col_softmax()
{
    int n = blockIdx.y;
    int t = blockIdx.x * 256 + threadIdx.x;
    const float* x = g_logitD + (size_t)n * LO * LDC;
    float mx = -3.4e38f;
    for (int o = 0; o < LO; o++) mx = fmaxf(mx, x[(size_t)o * LDC + t]);
    float sum = 0.f;
    for (int o = 0; o < LO; o++) sum += expf(x[(size_t)o * LDC + t] - mx);
    float inv = 1.f / sum;
    int km = g_doc_mask[n*LDC + t];
    float* y = g_kq + (size_t)n * LO * LDC;
    for (int o = 0; o < LO; o++) {
        float e = expf(x[(size_t)o * LDC + t] - mx);
        y[(size_t)o * LDC + t] = (km && g_opt_mask[n*LO + o]) ? e * inv : 0.f;
    }
}

// ---------------------------------------------------------------------------
// Concat builders + final max
// ---------------------------------------------------------------------------
__global__ void k_feats()
{
    size_t idx = (size_t)blockIdx.x * 256 + threadIdx.x;
    size_t r = idx >> 10;
    int h = (int)(idx & 1023);
    int n = (int)(r >> 8);
    int o = (int)(r & 255);
    float cur = g_opt_enc[idx];
    float* xr = g_X + r * (7*HD);
    xr[h] = cur;
#pragma unroll
    for (int jj = 0; jj < 3; jj++) {
        float a = g_attnOpt[(((size_t)(n*3 + jj) * LO + o) << 10) + h];
        xr[(1 + 2*jj)*HD + h] = cur * a;
        xr[(2 + 2*jj)*HD + h] = cur - a;
    }
}

__global__ void k_concat2()
{
    size_t idx = (size_t)blockIdx.x * 256 + threadIdx.x;
    size_t r = idx >> 10;
    int h = (int)(idx & 1023);
    float* xr = g_X + r * (2*HD);
    xr[h] = g_opt_enc[idx];
    xr[HD + h] = g_corr[idx];
}

__global__ void k_concat3()
{
    size_t idx = (size_t)blockIdx.x * 256 + threadIdx.x;
    size_t r = idx >> 10;
    int h = (int)(idx & 1023);
    float* xr = g_X + r * (3*HD);
    xr[h] = g_option[idx];
    xr[HD + h] = g_attnD[idx];
    xr[2*HD + h] = g_coattn[idx];
}

__global__ void k_concat4()
{
    size_t idx = (size_t)blockIdx.x * 256 + threadIdx.x;
    size_t r = idx >> 10;
    int h = (int)(idx & 1023);
    float f = g_fusion[idx];
    float a = g_attn2[idx];
    float* xr = g_X + r * (4*HD);
    xr[h] = f;
    xr[HD + h] = a;
    xr[2*HD + h] = f * a;
    xr[3*HD + h] = f - a;
}

__global__ void k_final(float* __restrict__ out)
{
    int n = blockIdx.y;
    int h = blockIdx.x * 256 + threadIdx.x;
    float mx = NEGV;
    for (int o = 0; o < LO; o++) {
        if (g_opt_mask[n*LO + o])
            mx = fmaxf(mx, g_fusion2[((size_t)(n*LO + o) << 10) + h]);
    }
    out[(size_t)n * HD + h] = mx;
}

// ---------------------------------------------------------------------------
// Launch
// ---------------------------------------------------------------------------
extern "C" void kernel_launch(void* const* d_in, const int* in_sizes, int n_in,
                              void* d_out, int out_size)
{
    const float* ll  = (const float*)d_in[0];
    const int*   am  = (const int*)d_in[1];
    const int*   fpw = (const int*)d_in[2];
    int base = (in_sizes[3] <= 8) ? 4 : 3;
    const float* attn_w1   = (const float*)d_in[base+0];
    const float* attn_w2   = (const float*)d_in[base+1];
    const float* attn_w3   = (const float*)d_in[base+2];
    const float* opt_w1    = (const float*)d_in[base+3];
    const float* opt_w2    = (const float*)d_in[base+4];
    const float* opt_w3    = (const float*)d_in[base+5];
    const float* self_w1   = (const float*)d_in[base+6];
    const float* self_w2   = (const float*)d_in[base+7];
    const float* self_w3   = (const float*)d_in[base+8];
    const float* attn_fc_w = (const float*)d_in[base+9];
    const float* attn_fc_b = (const float*)d_in[base+10];
    const float* comp_fc_w = (const float*)d_in[base+11];
    const float* comp_fc_b = (const float*)d_in[base+12];
    const float* gate_fc_w = (const float*)d_in[base+13];
    const float* gate_fc_b = (const float*)d_in[base+14];
    const float* self_fc_w = (const float*)d_in[base+15];
    const float* self_fc_b = (const float*)d_in[base+16];
    float* out = (float*)d_out;

    float *opt_enc, *doc_enc, *logitOpt, *attnOpt, *X, *corr, *option;
    float *logitD, *kq, *attnD, *cow, *coattn, *fusion, *logitS, *attn2, *fusion2;
    float *rowq, *rowk, *rowkd;
    int *opt_mask, *doc_mask;
    cudaGetSymbolAddress((void**)&opt_enc,  g_opt_enc);
    cudaGetSymbolAddress((void**)&doc_enc,  g_doc_enc);
    cudaGetSymbolAddress((void**)&logitOpt, g_logitOpt);
    cudaGetSymbolAddress((void**)&attnOpt,  g_attnOpt);
    cudaGetSymbolAddress((void**)&X,        g_X);
    cudaGetSymbolAddress((void**)&corr,     g_corr);
    cudaGetSymbolAddress((void**)&option,   g_option);
    cudaGetSymbolAddress((void**)&logitD,   g_logitD);
    cudaGetSymbolAddress((void**)&kq,       g_kq);
    cudaGetSymbolAddress((void**)&attnD,    g_attnD);
    cudaGetSymbolAddress((void**)&cow,      g_cow);
    cudaGetSymbolAddress((void**)&coattn,   g_coattn);
    cudaGetSymbolAddress((void**)&fusion,   g_fusion);
    cudaGetSymbolAddress((void**)&logitS,   g_logitS);
    cudaGetSymbolAddress((void**)&attn2,    g_attn2);
    cudaGetSymbolAddress((void**)&fusion2,  g_fusion2);
    cudaGetSymbolAddress((void**)&rowq,     g_rowq);
    cudaGetSymbolAddress((void**)&rowk,     g_rowk);
    cudaGetSymbolAddress((void**)&rowkd,    g_rowkd);
    cudaGetSymbolAddress((void**)&opt_mask, g_opt_mask);
    cudaGetSymbolAddress((void**)&doc_mask, g_doc_mask);

    const int EW_BLOCKS = (MR * HD) / 256;   // 65536
    const dim3 FC_GRID(HD/128, MR/128);      // 8 x 128

    // 1) build encodings + masks
    k_build_opt<<<dim3(LO,  NRW), 256>>>(ll, am, fpw);
    k_build_doc<<<dim3(LDC, NRW), 256>>>(ll, am, fpw);

    // 2) opt-opt cross attention (192 pairs)
    k_rowdot<<<MR, 256>>>(opt_enc, opt_w1, rowq);
    k_rowdot<<<MR, 256>>>(opt_enc, opt_w2, rowk);
    k_gemm_nt<4><<<dim3(LO/128, LO/128, NPAIR), 256>>>(
        opt_enc, opt_enc, logitOpt, LO, LO, HD, 0,0,0,
        opt_w3, rowq, rowk, opt_mask, opt_mask, 0,0, 1);
    k_row_softmax<<<dim3(LO, NPAIR), 256>>>(logitOpt, LO, opt_mask, opt_mask, 0,0,0, 1);
    k_gemm_nn<<<dim3(HD/128, LO/128, NPAIR), 256>>>(
        logitOpt, opt_enc, attnOpt, LO, HD, LO, 0,0,0, 1);

    // 3) comp FC (K = 7H) via 3xFP16 tensor path
    k_feats<<<EW_BLOCKS, 256>>>();
    k_fc_mma<1><<<FC_GRID, 256>>>(X, comp_fc_w, corr, 7*HD, comp_fc_b, nullptr, nullptr);

    // 4) gate FC (K = 2H) with fused gate-combine -> option
    k_concat2<<<EW_BLOCKS, 256>>>();
    k_fc_mma<3><<<FC_GRID, 256>>>(X, gate_fc_w, option, 2*HD, gate_fc_b, opt_enc, corr);

    // 5) doc attention (with co-attention)
    k_rowdot<<<MR, 256>>>(option, attn_w1, rowq);
    k_rowdot<<<NRW*LDC, 256>>>(doc_enc, attn_w2, rowkd);
    k_gemm_nt<4><<<dim3(LDC/128, LO/128, NRW), 256>>>(
        option, doc_enc, logitD, LO, LDC, HD,
        (long)LO*HD, (long)LDC*HD, (long)LO*LDC,
        attn_w3, rowq, rowkd, opt_mask, doc_mask, LO, LDC, 0);
    k_col_softmax<<<dim3(LDC/256, NRW), 256>>>();
    k_row_softmax<<<dim3(LO, NRW), 256>>>(logitD, LDC, opt_mask, doc_mask,
        (long)LO*LDC, LO, LDC, 0);
    k_gemm_nn<<<dim3(HD/128, LO/128, NRW), 256>>>(
        logitD, doc_enc, attnD, LO, HD, LDC,
        (long)LO*LDC, (long)LDC*HD, (long)LO*HD, 0);
    k_gemm_nt<0><<<dim3(LO/128, LO/128, NRW), 256>>>(
        logitD, kq, cow, LO, LO, LDC,
        (long)LO*LDC, (long)LO*LDC, (long)LO*LO,
        nullptr, nullptr, nullptr, nullptr, nullptr, 0,0, 0);
    k_gemm_nn<<<dim3(HD/128, LO/128, NRW), 256>>>(
        cow, option, coattn, LO, HD, LO,
        (long)LO*LO, (long)LO*HD, (long)LO*HD, 0);

    // 6) attn FC (K = 3H) -> fusion
    k_concat3<<<EW_BLOCKS, 256>>>();
    k_fc_mma<1><<<FC_GRID, 256>>>(X, attn_fc_w, fusion, 3*HD, attn_fc_b, nullptr, nullptr);

    // 7) self attention
    k_rowdot<<<MR, 256>>>(fusion, self_w1, rowq);
    k_rowdot<<<MR, 256>>>(fusion, self_w2, rowk);
    k_gemm_nt<4><<<dim3(LO/128, LO/128, NRW), 256>>>(
        fusion, fusion, logitS, LO, LO, HD,
        (long)LO*HD, (long)LO*HD, (long)LO*LO,
        self_w3, rowq, rowk, opt_mask, opt_mask, LO, LO, 0);
    k_row_softmax<<<dim3(LO, NRW), 256>>>(logitS, LO, opt_mask, opt_mask,
        (long)LO*LO, LO, LO, 0);
    k_gemm_nn<<<dim3(HD/128, LO/128, NRW), 256>>>(
        logitS, fusion, attn2, LO, HD, LO,
        (long)LO*LO, (long)LO*HD, (long)LO*HD, 0);

    // 8) self FC (K = 4H) -> fusion2
    k_concat4<<<EW_BLOCKS, 256>>>();
    k_fc_mma<2><<<FC_GRID, 256>>>(X, self_fc_w, fusion2, 4*HD, self_fc_b, nullptr, nullptr);

    // 9) masked max over option positions
    k_final<<<dim3(HD/256, NRW), 256>>>(out);
}